// round 12
// baseline (speedup 1.0000x reference)
#include <cuda_runtime.h>
#include <cstdint>

// Problem constants (match reference)
static constexpr int B_ = 4096;   // batch
static constexpr int D_ = 512;    // theta dim
static constexpr int K_ = 128;    // mixture comps
static constexpr int A_ = 32;     // alpha dim
static constexpr int P_ = 16;     // hutchinson probes
static constexpr int DT_ = D_ / 64; // d-tiles in wm_loss (8)

// Scratch (device globals; no allocation allowed)
__device__ float g_mu[K_ * D_];        // mu[k][d]
__device__ float g_muT[D_ * K_];       // mu^T[d][k]
__device__ __align__(16) char g_q[K_ * D_ * 2];  // interleaved (hi, lo) int8: q=64*hi+lo=round(mu*1024)
__device__ float g_musq[K_];           // ||mu_k||^2
__device__ float g_S[B_ * K_];         // softmax weights
__device__ float g_traceP[P_][B_];     // per-probe  sum_k w y^2 - (sum_k w y)^2
__device__ float g_lossPart[DT_][B_];  // per-d-tile sum_d (m - theta)^2
__device__ double g_part[16];          // final partial sums

// ================= portable PTX helpers =================
__device__ __forceinline__ uint32_t smem_u32(const void* p) {
    uint32_t a;
    asm("{ .reg .u64 t; cvta.to.shared.u64 t, %1; cvt.u32.u64 %0, t; }"
        : "=r"(a) : "l"(p));
    return a;
}
__device__ __forceinline__ void ldsm_x4(uint32_t& r0, uint32_t& r1, uint32_t& r2,
                                        uint32_t& r3, uint32_t addr) {
    asm volatile("ldmatrix.sync.aligned.m8n8.x4.shared.b16 {%0,%1,%2,%3}, [%4];"
                 : "=r"(r0), "=r"(r1), "=r"(r2), "=r"(r3) : "r"(addr));
}
__device__ __forceinline__ void ldsm_x2(uint32_t& r0, uint32_t& r1, uint32_t addr) {
    asm volatile("ldmatrix.sync.aligned.m8n8.x2.shared.b16 {%0,%1}, [%2];"
                 : "=r"(r0), "=r"(r1) : "r"(addr));
}
__device__ __forceinline__ void imma_s8(int* c, uint32_t a0, uint32_t a1,
                                        uint32_t a2, uint32_t a3,
                                        uint32_t b0, uint32_t b1) {
    asm volatile(
        "mma.sync.aligned.m16n8k32.row.col.s32.s8.s8.s32 "
        "{%0,%1,%2,%3}, {%4,%5,%6,%7}, {%8,%9}, {%0,%1,%2,%3};"
        : "+r"(c[0]), "+r"(c[1]), "+r"(c[2]), "+r"(c[3])
        : "r"(a0), "r"(a1), "r"(a2), "r"(a3), "r"(b0), "r"(b1));
}
__device__ __forceinline__ void cp_async16(uint32_t dst, const void* src) {
    asm volatile("cp.async.cg.shared.global [%0], [%1], 16;"
                 :: "r"(dst), "l"(src) : "memory");
}
__device__ __forceinline__ void cp_commit_wait0() {
    asm volatile("cp.async.commit_group;" ::: "memory");
    asm volatile("cp.async.wait_group 0;" ::: "memory");
}
// 64B-row swizzle
__device__ __forceinline__ uint32_t sw64(uint32_t o) { return o ^ ((o >> 3) & 0x30u); }

// pack two Rademacher ints (0/1) into int8 pairs (+-64, +-1) per 16-bit lane:
// v=1 -> (64, 1) = 0x0140 ; v=0 -> (-64, -1) = 0xFFC0 (little endian: lo byte=+-64)
__device__ __forceinline__ uint32_t pk2(int v0, int v1) {
    return (v0 ? 0x0140u : 0xFFC0u) | (v1 ? 0x01400000u : 0xFFC00000u);
}

// ---------------- packed f32x2 helpers (FFMA2 path) ----------------
__device__ __forceinline__ unsigned long long ffma2(unsigned long long a,
                                                    unsigned long long b,
                                                    unsigned long long c) {
    unsigned long long d;
    asm("fma.rn.f32x2 %0, %1, %2, %3;" : "=l"(d) : "l"(a), "l"(b), "l"(c));
    return d;
}
__device__ __forceinline__ void unpack2(unsigned long long v, float& lo, float& hi) {
    asm("mov.b64 {%0, %1}, %2;" : "=f"(lo), "=f"(hi) : "l"(v));
}

// ---------------- K1: mu = alpha @ W, mu^T, ||mu_k||^2, int8 hi/lo -----------
__global__ void __launch_bounds__(128) mu_kernel(const float* __restrict__ alpha,
                                                 const float* __restrict__ W) {
    int k = blockIdx.x;
    int t = threadIdx.x;
    __shared__ float as[A_];
    if (t < A_) as[t] = alpha[k * A_ + t];
    __syncthreads();
    float sq = 0.f;
#pragma unroll
    for (int rep = 0; rep < D_ / 128; rep++) {
        int d = rep * 128 + t;
        float acc = 0.f;
#pragma unroll
        for (int a = 0; a < A_; a++) acc = fmaf(as[a], W[a * D_ + d], acc);
        g_mu[k * D_ + d] = acc;
        g_muT[(size_t)d * K_ + k] = acc;
        int q = __float2int_rn(acc * 1024.0f);
        q = max(-8159, min(8159, q));
        int hi = (q + 32) >> 6;          // round-to-nearest 64-split
        int lo = q - (hi << 6);          // in [-32, 31]
        char2 pr; pr.x = (char)hi; pr.y = (char)lo;
        *(char2*)&g_q[((size_t)k * D_ + d) * 2] = pr;
        sq = fmaf(acc, acc, sq);
    }
    __shared__ float red[4];
#pragma unroll
    for (int off = 16; off; off >>= 1) sq += __shfl_xor_sync(0xffffffffu, sq, off);
    if ((t & 31) == 0) red[t >> 5] = sq;
    __syncthreads();
    if (t == 0) g_musq[k] = red[0] + red[1] + red[2] + red[3];
}

// ---------------- K2: theta @ mu^T + fused row softmax -> g_S ----------------
// BM=32 (128 CTAs for better chip fill), BN=128, BK=32, f32x2 accumulate.
__global__ void __launch_bounds__(256)
logits_softmax_kernel(const float* __restrict__ X) {
    __shared__ float2 As2[32][37];
    __shared__ float  Bs[32][128];
    __shared__ float  musq_s[K_];

    const int rowbase = blockIdx.x * 32;
    const int tid = threadIdx.x;
    const int tx = tid & 15;
    const int ty = tid >> 4;
    if (tid < K_) musq_s[tid] = g_musq[tid];

    unsigned long long acc[2][4];
#pragma unroll
    for (int i = 0; i < 2; i++)
#pragma unroll
        for (int j = 0; j < 4; j++) acc[i][j] = 0ull;

    for (int d0 = 0; d0 < D_; d0 += 32) {
        {
            int r = tid >> 3;
            int c4 = (tid & 7) << 2;
            float4 va = *(const float4*)(X + (size_t)(rowbase + r) * D_ + d0 + c4);
            As2[r][c4 + 0] = make_float2(va.x, va.x);
            As2[r][c4 + 1] = make_float2(va.y, va.y);
            As2[r][c4 + 2] = make_float2(va.z, va.z);
            As2[r][c4 + 3] = make_float2(va.w, va.w);
        }
#pragma unroll
        for (int it = 0; it < 4; it++) {
            int idx = tid + it * 256;
            int kk = idx >> 5;
            int n4 = (idx & 31) << 2;
            *(float4*)&Bs[kk][n4] = *(const float4*)(g_muT + (size_t)(d0 + kk) * K_ + n4);
        }
        __syncthreads();
#pragma unroll 8
        for (int kk = 0; kk < 32; kk++) {
            ulonglong2 b01 = *(const ulonglong2*)&Bs[kk][tx * 8];
            ulonglong2 b23 = *(const ulonglong2*)&Bs[kk][tx * 8 + 4];
#pragma unroll
            for (int i = 0; i < 2; i++) {
                unsigned long long aa = *(const unsigned long long*)&As2[ty * 2 + i][kk];
                acc[i][0] = ffma2(aa, b01.x, acc[i][0]);
                acc[i][1] = ffma2(aa, b01.y, acc[i][1]);
                acc[i][2] = ffma2(aa, b23.x, acc[i][2]);
                acc[i][3] = ffma2(aa, b23.y, acc[i][3]);
            }
        }
        __syncthreads();
    }

#pragma unroll
    for (int i = 0; i < 2; i++) {
        int row = rowbase + ty * 2 + i;
        float l[8];
#pragma unroll
        for (int j = 0; j < 4; j++) unpack2(acc[i][j], l[2 * j], l[2 * j + 1]);
#pragma unroll
        for (int j = 0; j < 8; j++) l[j] -= 0.5f * musq_s[tx * 8 + j];
        float m = l[0];
#pragma unroll
        for (int j = 1; j < 8; j++) m = fmaxf(m, l[j]);
#pragma unroll
        for (int off = 8; off; off >>= 1) m = fmaxf(m, __shfl_xor_sync(0xffffffffu, m, off));
        float e[8], s = 0.f;
#pragma unroll
        for (int j = 0; j < 8; j++) { e[j] = expf(l[j] - m); s += e[j]; }
#pragma unroll
        for (int off = 8; off; off >>= 1) s += __shfl_xor_sync(0xffffffffu, s, off);
        float inv = 1.0f / s;
        float4 w0 = make_float4(e[0] * inv, e[1] * inv, e[2] * inv, e[3] * inv);
        float4 w1 = make_float4(e[4] * inv, e[5] * inv, e[6] * inv, e[7] * inv);
        *(float4*)&g_S[(size_t)row * K_ + tx * 8 + 0] = w0;
        *(float4*)&g_S[(size_t)row * K_ + tx * 8 + 4] = w1;
    }
}

// ---------------- K3: probe trace via int8 IMMA (interleaved hi/lo) ----------
// Per CTA: probe p, 128 rows x 128 comps. A[r, 2d+{0,1}] = (+-64, +-1),
// B[n, 2d+{0,1}] = (hi, lo): acc = sum_d +-(64*hi+lo) = 1024 * y. Exact int32.
// Chunk = 32 d-values = 64 int8 k = two m16n8k32 k-steps. Double buffered.
static constexpr int BKD = 32;                // d per chunk
static constexpr int NCHI = D_ / BKD;         // 16
static constexpr int TILEB = 128 * 64;        // 8 KB per int8 tile

__global__ void __launch_bounds__(256)
probe_imma_kernel(const int* __restrict__ Vint) {
    __shared__ __align__(1024) char smA[2][TILEB];
    __shared__ __align__(1024) char smB[2][TILEB];
    __shared__ float red1[128], red2[128];

    const int tid = threadIdx.x, wid = tid >> 5, lane = tid & 31;
    const int wm = wid & 3, wn = wid >> 2;
    const int g = lane >> 2, tig = lane & 3;
    const int p = blockIdx.y, rowbase = blockIdx.x * 128;
    const size_t vbase = (size_t)p * B_ * D_ + (size_t)rowbase * D_;

    const uint32_t aB = smem_u32(smA);
    const uint32_t bB = smem_u32(smB);

    // Fill indexing: u = tid + i*256, i<2: r=u>>2 (0..127), g16=u&3 (16B unit)
    const int fr0 = tid >> 2, fg0 = tid & 3;
    const int fr1 = (tid + 256) >> 2, fg1 = (tid + 256) & 3;

    int acc[2][8][4];
#pragma unroll
    for (int i = 0; i < 2; i++)
#pragma unroll
        for (int j = 0; j < 8; j++)
#pragma unroll
            for (int q = 0; q < 4; q++) acc[i][j][q] = 0;

    // ldmatrix lane address offsets (before ks/buf adjustment)
    const uint32_t aOff0 = (uint32_t)((wm * 32 + ((lane >> 3) & 1) * 8 + (lane & 7)) * 64 +
                                      (lane >> 4) * 16);
    const uint32_t bOffL = (uint32_t)((wn * 64 + (lane & 7)) * 64 + ((lane >> 3) & 1) * 16);

    // ---- prologue: fill buf0 with chunk 0; prefetch ints for chunk 1 ----
    int4 R2[4];
    {
#pragma unroll
        for (int i = 0; i < 2; i++) {
            int r = i ? fr1 : fr0, g16 = i ? fg1 : fg0;
            const int* src = Vint + vbase + (size_t)r * D_ + g16 * 8;
            int4 a = *(const int4*)(src);
            int4 b = *(const int4*)(src + 4);
            uint4 w;
            w.x = pk2(a.x, a.y); w.y = pk2(a.z, a.w);
            w.z = pk2(b.x, b.y); w.w = pk2(b.z, b.w);
            *(uint4*)(smA[0] + sw64((uint32_t)(r * 64 + g16 * 16))) = w;
        }
#pragma unroll
        for (int i = 0; i < 2; i++) {
            int n = i ? fr1 : fr0, c16 = i ? fg1 : fg0;
            cp_async16(bB + sw64((uint32_t)(n * 64 + c16 * 16)),
                       g_q + (size_t)n * (D_ * 2) + c16 * 16);
        }
#pragma unroll
        for (int i = 0; i < 2; i++) {
            int r = i ? fr1 : fr0, g16 = i ? fg1 : fg0;
            const int* src = Vint + vbase + (size_t)r * D_ + BKD + g16 * 8;
            R2[2 * i] = *(const int4*)(src);
            R2[2 * i + 1] = *(const int4*)(src + 4);
        }
        cp_commit_wait0();
        __syncthreads();
    }

    for (int ch = 0; ch < NCHI; ch++) {
        const int buf = ch & 1;
        const uint32_t aBuf = aB + buf * TILEB;
        const uint32_t bBuf = bB + buf * TILEB;
        // ---- MMA on current buffer ----
#pragma unroll
        for (int ks = 0; ks < 2; ks++) {
            uint32_t a0[4], a1[4];
            ldsm_x4(a0[0], a0[1], a0[2], a0[3], aBuf + sw64(aOff0 + ks * 32));
            ldsm_x4(a1[0], a1[1], a1[2], a1[3], aBuf + sw64(aOff0 + 16 * 64 + ks * 32));
#pragma unroll
            for (int nf = 0; nf < 8; nf++) {
                uint32_t b0, b1;
                ldsm_x2(b0, b1, bBuf + sw64(bOffL + (uint32_t)(nf * 8 * 64) + ks * 32));
                imma_s8(acc[0][nf], a0[0], a0[1], a0[2], a0[3], b0, b1);
                imma_s8(acc[1][nf], a1[0], a1[1], a1[2], a1[3], b0, b1);
            }
        }
        // ---- fill other buffer with chunk ch+1 ----
        if (ch + 1 < NCHI) {
            char* aN = smA[buf ^ 1];
#pragma unroll
            for (int i = 0; i < 2; i++) {
                int r = i ? fr1 : fr0, g16 = i ? fg1 : fg0;
                uint4 w;
                w.x = pk2(R2[2 * i].x, R2[2 * i].y);
                w.y = pk2(R2[2 * i].z, R2[2 * i].w);
                w.z = pk2(R2[2 * i + 1].x, R2[2 * i + 1].y);
                w.w = pk2(R2[2 * i + 1].z, R2[2 * i + 1].w);
                *(uint4*)(aN + sw64((uint32_t)(r * 64 + g16 * 16))) = w;
            }
            if (ch + 2 < NCHI) {
#pragma unroll
                for (int i = 0; i < 2; i++) {
                    int r = i ? fr1 : fr0, g16 = i ? fg1 : fg0;
                    const int* src = Vint + vbase + (size_t)r * D_ + (ch + 2) * BKD + g16 * 8;
                    R2[2 * i] = *(const int4*)(src);
                    R2[2 * i + 1] = *(const int4*)(src + 4);
                }
            }
            const uint32_t bN = bB + (buf ^ 1) * TILEB;
#pragma unroll
            for (int i = 0; i < 2; i++) {
                int n = i ? fr1 : fr0, c16 = i ? fg1 : fg0;
                cp_async16(bN + sw64((uint32_t)(n * 64 + c16 * 16)),
                           g_q + (size_t)n * (D_ * 2) + (ch + 1) * 64 + c16 * 16);
            }
            cp_commit_wait0();
            __syncthreads();
        }
    }

    // ---- epilogue: s1 = sum_k w y^2, s2 = sum_k w y with y = acc/1024 ----
    const float inv1024 = 1.0f / 1024.0f;
    float s1[2][2] = {{0.f, 0.f}, {0.f, 0.f}};
    float s2[2][2] = {{0.f, 0.f}, {0.f, 0.f}};
#pragma unroll
    for (int mf = 0; mf < 2; mf++) {
        int r0 = rowbase + wm * 32 + mf * 16 + g;
#pragma unroll
        for (int nf = 0; nf < 8; nf++) {
            int col = wn * 64 + nf * 8 + tig * 2;
            float2 w0 = __ldg((const float2*)&g_S[(size_t)r0 * K_ + col]);
            float2 w1 = __ldg((const float2*)&g_S[(size_t)(r0 + 8) * K_ + col]);
            float c0 = (float)acc[mf][nf][0] * inv1024;
            float c1 = (float)acc[mf][nf][1] * inv1024;
            float c2 = (float)acc[mf][nf][2] * inv1024;
            float c3 = (float)acc[mf][nf][3] * inv1024;
            s1[mf][0] = fmaf(w0.x * c0, c0, fmaf(w0.y * c1, c1, s1[mf][0]));
            s2[mf][0] = fmaf(w0.x, c0, fmaf(w0.y, c1, s2[mf][0]));
            s1[mf][1] = fmaf(w1.x * c2, c2, fmaf(w1.y * c3, c3, s1[mf][1]));
            s2[mf][1] = fmaf(w1.x, c2, fmaf(w1.y, c3, s2[mf][1]));
        }
    }
#pragma unroll
    for (int mf = 0; mf < 2; mf++)
#pragma unroll
        for (int h = 0; h < 2; h++)
#pragma unroll
            for (int off = 1; off < 4; off <<= 1) {
                s1[mf][h] += __shfl_xor_sync(0xffffffffu, s1[mf][h], off);
                s2[mf][h] += __shfl_xor_sync(0xffffffffu, s2[mf][h], off);
            }
    __syncthreads();
    if (wn == 1 && tig == 0) {
#pragma unroll
        for (int mf = 0; mf < 2; mf++)
#pragma unroll
            for (int h = 0; h < 2; h++) {
                int rl = wm * 32 + mf * 16 + h * 8 + g;
                red1[rl] = s1[mf][h];
                red2[rl] = s2[mf][h];
            }
    }
    __syncthreads();
    if (wn == 0 && tig == 0) {
#pragma unroll
        for (int mf = 0; mf < 2; mf++)
#pragma unroll
            for (int h = 0; h < 2; h++) {
                int rl = wm * 32 + mf * 16 + h * 8 + g;
                float t1 = s1[mf][h] + red1[rl];
                float t2 = s2[mf][h] + red2[rl];
                g_traceP[p][rowbase + rl] = t1 - t2 * t2;
            }
    }
}

// ---------------- K4: M = w @ mu, fused sum_d (m - theta)^2, f32x2 ----------
__global__ void __launch_bounds__(256)
wm_loss_kernel(const float* __restrict__ theta) {
    __shared__ float2 Ws2[64][33];
    __shared__ float  Ms[32][68];

    const int rowbase = blockIdx.x * 64;
    const int d0 = blockIdx.y * 64;
    const int tid = threadIdx.x;
    const int tx = tid & 15;
    const int ty = tid >> 4;

    unsigned long long acc[4][2];
#pragma unroll
    for (int i = 0; i < 4; i++) { acc[i][0] = 0ull; acc[i][1] = 0ull; }

    for (int k0 = 0; k0 < K_; k0 += 32) {
        {
            int r = tid >> 2;
            int c8 = (tid & 3) * 8;
            float4 v0 = *(const float4*)&g_S[(size_t)(rowbase + r) * K_ + k0 + c8];
            float4 v1 = *(const float4*)&g_S[(size_t)(rowbase + r) * K_ + k0 + c8 + 4];
            Ws2[r][c8 + 0] = make_float2(v0.x, v0.x);
            Ws2[r][c8 + 1] = make_float2(v0.y, v0.y);
            Ws2[r][c8 + 2] = make_float2(v0.z, v0.z);
            Ws2[r][c8 + 3] = make_float2(v0.w, v0.w);
            Ws2[r][c8 + 4] = make_float2(v1.x, v1.x);
            Ws2[r][c8 + 5] = make_float2(v1.y, v1.y);
            Ws2[r][c8 + 6] = make_float2(v1.z, v1.z);
            Ws2[r][c8 + 7] = make_float2(v1.w, v1.w);
        }
#pragma unroll
        for (int it = 0; it < 2; it++) {
            int idx = tid + it * 256;
            int kk = idx >> 4;
            int c4 = (idx & 15) << 2;
            *(float4*)&Ms[kk][c4] = *(const float4*)&g_mu[(size_t)(k0 + kk) * D_ + d0 + c4];
        }
        __syncthreads();
#pragma unroll 8
        for (int kk = 0; kk < 32; kk++) {
            unsigned long long b0 = *(const unsigned long long*)&Ms[kk][tx * 4];
            unsigned long long b1 = *(const unsigned long long*)&Ms[kk][tx * 4 + 2];
#pragma unroll
            for (int i = 0; i < 4; i++) {
                unsigned long long aa = *(const unsigned long long*)&Ws2[ty * 4 + i][kk];
                acc[i][0] = ffma2(aa, b0, acc[i][0]);
                acc[i][1] = ffma2(aa, b1, acc[i][1]);
            }
        }
        __syncthreads();
    }

#pragma unroll
    for (int i = 0; i < 4; i++) {
        int row = rowbase + ty * 4 + i;
        float m0, m1, m2, m3;
        unpack2(acc[i][0], m0, m1);
        unpack2(acc[i][1], m2, m3);
        float4 th = *(const float4*)(theta + (size_t)row * D_ + d0 + tx * 4);
        float d0f = m0 - th.x, d1f = m1 - th.y, d2f = m2 - th.z, d3f = m3 - th.w;
        float s = fmaf(d0f, d0f, fmaf(d1f, d1f, fmaf(d2f, d2f, d3f * d3f)));
#pragma unroll
        for (int off = 8; off; off >>= 1) s += __shfl_xor_sync(0xffffffffu, s, off);
        if (tx == 0) g_lossPart[blockIdx.y][row] = s;
    }
}

// ---------------- K5/K6: two-stage final reduction ---------------------------
__global__ void __launch_bounds__(256)
final_partial(const int* __restrict__ pN) {
    int b = blockIdx.x * 256 + threadIdx.x;
    float Nf = (float)pN[0];
    float temper = Nf / (Nf + 1.0f);
    float tr = 0.f;
#pragma unroll
    for (int p = 0; p < P_; p++) tr += g_traceP[p][b];
    float ls = 0.f;
#pragma unroll
    for (int dt = 0; dt < DT_; dt++) ls += g_lossPart[dt][b];
    double val = (double)(0.5f * temper * temper * ls
                          + temper * (tr * (1.0f / (float)P_) - (float)D_));
    __shared__ double sd[256];
    int t = threadIdx.x;
    sd[t] = val;
    __syncthreads();
    for (int s = 128; s; s >>= 1) {
        if (t < s) sd[t] += sd[t + s];
        __syncthreads();
    }
    if (t == 0) g_part[blockIdx.x] = sd[0];
}

__global__ void final_sum(float* __restrict__ out) {
    if (threadIdx.x == 0) {
        double acc = 0.0;
#pragma unroll
        for (int i = 0; i < 16; i++) acc += g_part[i];
        out[0] = (float)(acc / (double)B_);
    }
}

// ---------------- launch ------------------------------------------------------
extern "C" void kernel_launch(void* const* d_in, const int* in_sizes, int n_in,
                              void* d_out, int out_size) {
    const float* thetas = (const float*)d_in[0];  // [B, D]
    const float* alpha  = (const float*)d_in[1];  // [K, A]
    const float* W      = (const float*)d_in[2];  // [A, D]
    const int*   v_int  = (const int*)d_in[3];    // [P, B, D]
    const int*   pN     = (const int*)d_in[4];    // N_dataset
    float* out = (float*)d_out;

    mu_kernel<<<K_, 128>>>(alpha, W);
    logits_softmax_kernel<<<B_ / 32, 256>>>(thetas);              // logits + softmax
    probe_imma_kernel<<<dim3(B_ / 128, P_), 256>>>(v_int);        // int8 IMMA traces
    wm_loss_kernel<<<dim3(B_ / 64, D_ / 64), 256>>>(thetas);      // ||g||^2 parts
    final_partial<<<16, 256>>>(pN);
    final_sum<<<1, 32>>>(out);
}